// round 1
// baseline (speedup 1.0000x reference)
#include <cuda_runtime.h>
#include <cuda_bf16.h>
#include <cstdint>

// Problem constants (fixed by the dataset):
//   N = 100000 nodes, E = 1,600,000 edges, F_IN = 256, F_OUT = 128
// d_in order: input_features [N*256] f32, edge_rows [E] i32, edge_cols [E] i32,
//             edge_vals [E] f32, W [128*256] f32, b [128] f32
// d_out: [N*128] f32

#define F_IN   256
#define F_OUT  128
#define MAX_N  100000

// Scratch for the dense "transformed = X @ W^T + b" result (51.2 MB).
__device__ float g_transformed[(size_t)MAX_N * F_OUT];

// ---------------------------------------------------------------------------
// Phase 1: fp32 tiled GEMM  T[m][o] = sum_k X[m][k] * W[o][k] + b[o]
// Tile 128x128, BK=16, 256 threads, 8x8 register micro-tile per thread.
// ---------------------------------------------------------------------------
#define BM 128
#define BN 128
#define BK 16

__global__ __launch_bounds__(256) void gemm_bias_kernel(
    const float* __restrict__ X,
    const float* __restrict__ W,
    const float* __restrict__ bias,
    int M)
{
    __shared__ __align__(16) float Xs[BK][BM + 4];
    __shared__ __align__(16) float Ws[BK][BN + 4];

    const int tid = threadIdx.x;
    const int tx  = tid & 15;   // 0..15 -> output-feature octet
    const int ty  = tid >> 4;   // 0..15 -> row octet
    const int m0  = blockIdx.x * BM;

    // global->smem load mapping: 512 float4 per tile per operand, 2 per thread
    const int lr = tid >> 2;          // 0..63
    const int lc = (tid & 3) << 2;    // 0,4,8,12  (k-offset within tile)

    float acc[8][8];
#pragma unroll
    for (int i = 0; i < 8; ++i)
#pragma unroll
        for (int j = 0; j < 8; ++j) acc[i][j] = 0.0f;

    for (int k0 = 0; k0 < F_IN; k0 += BK) {
#pragma unroll
        for (int h = 0; h < 2; ++h) {
            const int mrow = m0 + lr + h * 64;
            float4 xv = make_float4(0.f, 0.f, 0.f, 0.f);
            if (mrow < M)
                xv = *(const float4*)(X + (size_t)mrow * F_IN + k0 + lc);
            Xs[lc + 0][lr + h * 64] = xv.x;
            Xs[lc + 1][lr + h * 64] = xv.y;
            Xs[lc + 2][lr + h * 64] = xv.z;
            Xs[lc + 3][lr + h * 64] = xv.w;

            const int orow = lr + h * 64;   // always < 128
            const float4 wv = *(const float4*)(W + (size_t)orow * F_IN + k0 + lc);
            Ws[lc + 0][orow] = wv.x;
            Ws[lc + 1][orow] = wv.y;
            Ws[lc + 2][orow] = wv.z;
            Ws[lc + 3][orow] = wv.w;
        }
        __syncthreads();

#pragma unroll
        for (int kk = 0; kk < BK; ++kk) {
            float a[8], bb[8];
            *(float4*)&a[0]  = *(const float4*)&Xs[kk][ty * 8];
            *(float4*)&a[4]  = *(const float4*)&Xs[kk][ty * 8 + 4];
            *(float4*)&bb[0] = *(const float4*)&Ws[kk][tx * 8];
            *(float4*)&bb[4] = *(const float4*)&Ws[kk][tx * 8 + 4];
#pragma unroll
            for (int i = 0; i < 8; ++i)
#pragma unroll
                for (int j = 0; j < 8; ++j)
                    acc[i][j] = fmaf(a[i], bb[j], acc[i][j]);
        }
        __syncthreads();
    }

    // epilogue: add bias, write transformed
    const float4 b0 = *(const float4*)&bias[tx * 8];
    const float4 b1 = *(const float4*)&bias[tx * 8 + 4];
#pragma unroll
    for (int i = 0; i < 8; ++i) {
        const int m = m0 + ty * 8 + i;
        if (m < M) {
            float4 o0, o1;
            o0.x = acc[i][0] + b0.x; o0.y = acc[i][1] + b0.y;
            o0.z = acc[i][2] + b0.z; o0.w = acc[i][3] + b0.w;
            o1.x = acc[i][4] + b1.x; o1.y = acc[i][5] + b1.y;
            o1.z = acc[i][6] + b1.z; o1.w = acc[i][7] + b1.w;
            float* dst = &g_transformed[(size_t)m * F_OUT + tx * 8];
            *(float4*)dst       = o0;
            *(float4*)(dst + 4) = o1;
        }
    }
}

// ---------------------------------------------------------------------------
// Phase 2: edge scatter.  One warp per edge:
//   out[row] += val * transformed[col]   (128 floats = 1 float4 per lane)
// Uses vectorized reduction red.global.add.v4.f32 (sm_90+).
// ---------------------------------------------------------------------------
__global__ __launch_bounds__(256) void spmm_scatter_kernel(
    const int*   __restrict__ rows,
    const int*   __restrict__ cols,
    const float* __restrict__ vals,
    float*       __restrict__ out,
    int E)
{
    const int warp = (int)((blockIdx.x * (unsigned)blockDim.x + threadIdx.x) >> 5);
    const int lane = threadIdx.x & 31;
    if (warp >= E) return;

    const int   r = __ldg(&rows[warp]);
    const int   c = __ldg(&cols[warp]);
    const float v = __ldg(&vals[warp]);

    const float4 t = __ldg((const float4*)(g_transformed + (size_t)c * F_OUT) + lane);

    float* dst = out + (size_t)r * F_OUT + lane * 4;
    asm volatile(
        "red.global.add.v4.f32 [%0], {%1, %2, %3, %4};"
        :
        : "l"(dst), "f"(t.x * v), "f"(t.y * v), "f"(t.z * v), "f"(t.w * v)
        : "memory");
}

// ---------------------------------------------------------------------------
// Launch
// ---------------------------------------------------------------------------
extern "C" void kernel_launch(void* const* d_in, const int* in_sizes, int n_in,
                              void* d_out, int out_size)
{
    const float* X    = (const float*)d_in[0];
    const int*   er   = (const int*)  d_in[1];
    const int*   ec   = (const int*)  d_in[2];
    const float* ev   = (const float*)d_in[3];
    const float* W    = (const float*)d_in[4];
    const float* bias = (const float*)d_in[5];
    float* out = (float*)d_out;

    const int M = in_sizes[0] / F_IN;   // 100000
    const int E = in_sizes[1];          // 1600000

    // out is poisoned; the scatter accumulates, so zero it first.
    cudaMemsetAsync(d_out, 0, (size_t)out_size * sizeof(float));

    gemm_bias_kernel<<<(M + BM - 1) / BM, 256>>>(X, W, bias, M);

    const int warps_per_block = 256 / 32;
    const int blocks = (E + warps_per_block - 1) / warps_per_block;
    spmm_scatter_kernel<<<blocks, 256>>>(er, ec, ev, out, E);
}